// round 12
// baseline (speedup 1.0000x reference)
#include <cuda_runtime.h>
#include <stdint.h>

#define NSEG   16384
#define SEGLEN 1024
#define KSEL   128
#define NTHR   256
#define WPB    8
#define NBLK   (NSEG / WPB)

// Gather everything x >= 0.84. Bins: f = x*1280 - 1075.2; band bins 0..95
// cover [0.84, 0.915); bin 96 = hi (x >= ~0.915).
#define B_LO   0.84f
#define INV_W  1280.0f
#define F_C    (-1075.2f)
#define NBAND  96
#define HIBIN  96
#define SLOTS  32      // 32 slots/lane: a lane gathers <=32 -> can NEVER overflow
#define BBUFN  8
#define NSLOT  256

__device__ float    g_part[NSLOT];   // zero-init at load
__device__ unsigned g_done = 0;

#define FULLM 0xffffffffu

__device__ __forceinline__ float warpSumF(float v) {
    #pragma unroll
    for (int o = 16; o; o >>= 1) v += __shfl_xor_sync(FULLM, v, o);
    return v;
}

__device__ __forceinline__ uint32_t smem_u32(const void* p) {
    uint32_t a;
    asm("{ .reg .u64 t; cvta.to.shared.u64 t, %1; cvt.u32.u64 %0, t; }"
        : "=r"(a) : "l"(p));
    return a;
}

__global__ __launch_bounds__(NTHR, 6)
void mil_kernel(const float* __restrict__ y_pred, const float* __restrict__ y,
                float* __restrict__ out) {
    __shared__ int   s_hist[WPB][HIBIN + 1];
    __shared__ float s_gath[WPB][SLOTS * 32];
    __shared__ float s_bbuf[WPB][BBUFN];
    __shared__ int   s_bcnt[WPB];
    __shared__ float s_red[WPB];
    __shared__ int   s_islast;

    const int tid  = threadIdx.x;
    const int lane = tid & 31;
    const int w    = tid >> 5;
    const int seg  = blockIdx.x * WPB + w;

    int*   hist = &s_hist[w][0];
    float* gath = &s_gath[w][0];

    // warp-local init (no block barrier in hot path)
    hist[lane] = 0; hist[lane + 32] = 0; hist[lane + 64] = 0;
    if (lane == 0) { hist[HIBIN] = 0; s_bcnt[w] = 0; }
    __syncwarp();

    const uint32_t gath_b = smem_u32(gath) + lane * 4;

    const float4* base = reinterpret_cast<const float4*>(y_pred + (size_t)seg * SEGLEN);
    const float t = __ldg(y + (size_t)seg * SEGLEN);   // label: segment-constant

    // ---- pass 1: 3 instr/elem — gather all x >= B_LO (running addr = counter) ----
    uint32_t addr = gath_b;
    const float blo = B_LO;
    #pragma unroll
    for (int h = 0; h < 2; h++) {
        float4 q0 = base[lane + (h * 4 + 0) * 32];
        float4 q1 = base[lane + (h * 4 + 1) * 32];
        float4 q2 = base[lane + (h * 4 + 2) * 32];
        float4 q3 = base[lane + (h * 4 + 3) * 32];
        float xs[16] = {q0.x, q0.y, q0.z, q0.w, q1.x, q1.y, q1.z, q1.w,
                        q2.x, q2.y, q2.z, q2.w, q3.x, q3.y, q3.z, q3.w};
        #pragma unroll
        for (int j = 0; j < 16; j++) {
            asm volatile(
                "{\n\t"
                ".reg .pred p;\n\t"
                "setp.ge.f32 p, %1, %2;\n\t"
                "@p st.shared.f32 [%0], %1;\n\t"
                "@p add.u32 %0, %0, 128;\n\t"
                "}"
                : "+r"(addr)
                : "f"(xs[j]), "f"(blo)
                : "memory");
        }
    }
    __syncwarp();

    const uint32_t mycnt  = (addr - gath_b) >> 7;          // <= 32 always
    const uint32_t maxcnt = __reduce_max_sync(FULLM, mycnt);

    // ---- pass 2: sum + histogram over gathered (~4.9/lane) ----
    float S = 0.f;
    for (uint32_t k = 0; k < maxcnt; k++) {
        if (k < mycnt) {
            float x = gath[lane + k * 32];
            S += x;
            int b = __float2int_rd(fmaf(x, INV_W, F_C));
            b = min(max(b, 0), HIBIN);                     // bin 96 = hi
            atomicAdd(&hist[b], 1);
        }
    }
    __syncwarp();
    const float S_all = warpSumF(S);                       // sum of ALL gathered
    const int   c_hi  = hist[HIBIN];                       // LDS broadcast
    const int   need  = KSEL - c_hi;

    // ---- suffix scan of 96 band bins; locate boundary bin b* ----
    const int c0 = hist[3 * lane], c1 = hist[3 * lane + 1], c2 = hist[3 * lane + 2];
    const int own = c0 + c1 + c2;
    int inc = own;
    #pragma unroll
    for (int o = 1; o < 32; o <<= 1) {
        int v = __shfl_down_sync(FULLM, inc, o);
        if (lane + o < 32) inc += v;
    }
    const int exc   = inc - own;
    const int total = __shfl_sync(FULLM, inc, 0);          // band count

    bool fb = (need <= 0) || (total < need);

    int bstar = 0, above = 0;
    {
        bool here = !fb && (exc < need) && (need <= inc);
        int lb = 0, la = 0;
        if (here) {
            if      (exc + c2 >= need)      { lb = 3 * lane + 2; la = exc; }
            else if (exc + c2 + c1 >= need) { lb = 3 * lane + 1; la = exc + c2; }
            else                            { lb = 3 * lane;     la = exc + c2 + c1; }
        }
        unsigned bal = __ballot_sync(FULLM, here);
        if (bal == 0) fb = true;
        else {
            int src = __ffs(bal) - 1;
            bstar = __shfl_sync(FULLM, lb, src);
            above = __shfl_sync(FULLM, la, src);
        }
    }

    float loss = 0.f;    // valid on lane 0

    if (!fb) {
        // ---- pass 3: subtract bins < b*; gather boundary bin == b* ----
        float sub = 0.f;
        for (uint32_t k = 0; k < maxcnt; k++) {
            if (k < mycnt) {
                float x = gath[lane + k * 32];
                int b = __float2int_rd(fmaf(x, INV_W, F_C));
                b = min(max(b, 0), HIBIN);
                if (b < bstar) sub += x;
                else if (b == bstar) {
                    int i2 = atomicAdd(&s_bcnt[w], 1);
                    if (i2 < BBUFN) s_bbuf[w][i2] = x;
                }
            }
        }
        __syncwarp();
        const int mm = s_bcnt[w];
        if (mm > BBUFN) fb = true;
        else {
            const int r = need - above;                // keep r largest of boundary
            if (lane < mm) {
                unsigned mv = __float_as_uint(s_bbuf[w][lane]);  // positive: int order
                int rk = 0;
                for (int j = 0; j < mm; j++) {
                    unsigned xv = __float_as_uint(s_bbuf[w][j]);
                    rk += (xv > mv) || (xv == mv && j < lane);
                }
                if (rk >= r) sub += __uint_as_float(mv);         // excluded
            }
            sub = warpSumF(sub);
            if (lane == 0) {
                float p = (S_all - sub) * (1.0f / KSEL);
                loss = t * __logf(p) + (1.0f - t) * __logf(1.0f - p);
            }
        }
    }

    if (fb) {
        // ---- exact fallback: radix select, reload (L1/L2-hot, rare) ----
        unsigned prefix = 0;
        for (int bit = 30; bit >= 0; bit--) {
            unsigned test = prefix | (1u << bit);
            int cc = 0;
            #pragma unroll
            for (int c = 0; c < 8; c++) {
                float4 q = base[lane + c * 32];
                cc += (__float_as_uint(q.x) >= test) + (__float_as_uint(q.y) >= test)
                    + (__float_as_uint(q.z) >= test) + (__float_as_uint(q.w) >= test);
            }
            cc = __reduce_add_sync(FULLM, cc);
            if (cc >= KSEL) prefix = test;
        }
        float Sf = 0.f; int G = 0;
        #pragma unroll
        for (int c = 0; c < 8; c++) {
            float4 q = base[lane + c * 32];
            if (__float_as_uint(q.x) > prefix) { G++; Sf += q.x; }
            if (__float_as_uint(q.y) > prefix) { G++; Sf += q.y; }
            if (__float_as_uint(q.z) > prefix) { G++; Sf += q.z; }
            if (__float_as_uint(q.w) > prefix) { G++; Sf += q.w; }
        }
        Sf = warpSumF(Sf);
        G = __reduce_add_sync(FULLM, G);
        if (lane == 0) {
            float kthv = __uint_as_float(prefix);
            float p = (Sf + (float)(KSEL - G) * kthv) * (1.0f / KSEL);
            loss = t * __logf(p) + (1.0f - t) * __logf(1.0f - p);
        }
    }

    if (lane == 0) atomicAdd(&g_part[seg & (NSLOT - 1)], loss);

    // ---- fused finalize: last block reduces the 256 partials ----
    __syncthreads();
    if (tid == 0) {
        __threadfence();
        unsigned old = atomicAdd(&g_done, 1u);
        s_islast = (old == NBLK - 1) ? 1 : 0;
    }
    __syncthreads();
    if (s_islast) {
        __threadfence();
        float v = g_part[tid];
        g_part[tid] = 0.0f;                   // reset for next graph replay
        v = warpSumF(v);
        if (lane == 0) s_red[w] = v;
        __syncthreads();
        if (tid == 0) {
            float acc = 0.f;
            #pragma unroll
            for (int i = 0; i < WPB; i++) acc += s_red[i];
            out[0] = -acc * (1.0f / NSEG);
            g_done = 0;                       // reset for next graph replay
        }
    }
}

extern "C" void kernel_launch(void* const* d_in, const int* in_sizes, int n_in,
                              void* d_out, int out_size) {
    const float* y_pred = (const float*)d_in[0];
    const float* yv     = (const float*)d_in[1];
    (void)in_sizes; (void)n_in; (void)out_size;

    mil_kernel<<<NBLK, NTHR>>>(y_pred, yv, (float*)d_out);
}

// round 13
// speedup vs baseline: 1.3333x; 1.3333x over previous
#include <cuda_runtime.h>
#include <stdint.h>

#define NSEG   16384
#define SEGLEN 1024
#define KSEL   128
#define NTHR   256
#define WPB    8
#define NBLK   (NSEG / WPB)

// Band [0.84, 0.915); bins f = x*1280 - 1075.2, truncated -> [0,95].
#define B_LO   0.84f
#define B_HI   0.915f
#define INV_W  1280.0f
#define F_C    (-1075.2f)
#define NBAND  96
#define SLOTS  32      // 32 slots/lane: can never overflow
#define CAP    8       // register-cached slots (covers ~99% of lanes)
#define BBUFN  8
#define NSLOT  256

__device__ float    g_part[NSLOT];   // zero-init at load
__device__ unsigned g_done = 0;

#define FULLM 0xffffffffu

__device__ __forceinline__ float warpSumF(float v) {
    #pragma unroll
    for (int o = 16; o; o >>= 1) v += __shfl_xor_sync(FULLM, v, o);
    return v;
}

__device__ __forceinline__ uint32_t smem_u32(const void* p) {
    uint32_t a;
    asm("{ .reg .u64 t; cvta.to.shared.u64 t, %1; cvt.u32.u64 %0, t; }"
        : "=r"(a) : "l"(p));
    return a;
}

__global__ __launch_bounds__(NTHR, 5)
void mil_kernel(const float* __restrict__ y_pred, const float* __restrict__ y,
                float* __restrict__ out) {
    __shared__ int   s_hist[WPB][NBAND];
    __shared__ float s_gath[WPB][SLOTS * 32];
    __shared__ float s_bbuf[WPB][BBUFN];
    __shared__ int   s_bcnt[WPB];
    __shared__ float s_red[WPB];
    __shared__ int   s_islast;

    const int tid  = threadIdx.x;
    const int lane = tid & 31;
    const int w    = tid >> 5;
    const int seg  = blockIdx.x * WPB + w;

    int*   hist = &s_hist[w][0];
    float* gath = &s_gath[w][0];

    // warp-local init (no block barrier in hot path)
    hist[lane] = 0; hist[lane + 32] = 0; hist[lane + 64] = 0;
    if (lane == 0) s_bcnt[w] = 0;
    __syncwarp();

    const uint32_t gath_b = smem_u32(gath) + lane * 4;

    const float4* base = reinterpret_cast<const float4*>(y_pred + (size_t)seg * SEGLEN);
    const float t = __ldg(y + (size_t)seg * SEGLEN);   // label: segment-constant

    // ---- pass 1: S/cge over x>=0.84 (predicated regs); band -> smem, 6 instr/elem ----
    float    S    = 0.f;
    uint32_t cge  = 0;
    uint32_t addr = gath_b;           // running addr doubles as counter (no wrap: SLOTS=32)
    const float blo = B_LO, bhi = B_HI;
    #pragma unroll
    for (int h = 0; h < 2; h++) {
        float4 q0 = base[lane + (h * 4 + 0) * 32];
        float4 q1 = base[lane + (h * 4 + 1) * 32];
        float4 q2 = base[lane + (h * 4 + 2) * 32];
        float4 q3 = base[lane + (h * 4 + 3) * 32];
        float xs[16] = {q0.x, q0.y, q0.z, q0.w, q1.x, q1.y, q1.z, q1.w,
                        q2.x, q2.y, q2.z, q2.w, q3.x, q3.y, q3.z, q3.w};
        #pragma unroll
        for (int j = 0; j < 16; j++) {
            asm volatile(
                "{\n\t"
                ".reg .pred p, q;\n\t"
                "setp.ge.f32 p, %3, %4;\n\t"
                "@p add.f32 %0, %0, %3;\n\t"
                "@p add.u32 %1, %1, 1;\n\t"
                "setp.lt.and.f32 q, %3, %5, p;\n\t"
                "@q st.shared.f32 [%2], %3;\n\t"
                "@q add.u32 %2, %2, 128;\n\t"
                "}"
                : "+f"(S), "+r"(cge), "+r"(addr)
                : "f"(xs[j]), "f"(blo), "f"(bhi)
                : "memory");
        }
    }
    __syncwarp();

    const uint32_t mycnt = (addr - gath_b) >> 7;           // band elems this lane (<=32)

    // ---- warp reduces ----
    const float S_all = warpSumF(S);
    const int   c_ge  = __reduce_add_sync(FULLM, (int)cge);

    // ---- register-cache first CAP slots (batched LDS, MLP 8) ----
    float rv[CAP];
    #pragma unroll
    for (int i = 0; i < CAP; i++) rv[i] = gath[lane + i * 32];  // garbage OK beyond mycnt

    // ---- pass 2: histogram band elements from registers ----
    #pragma unroll
    for (int i = 0; i < CAP; i++) {
        if ((uint32_t)i < mycnt) {
            int b = (int)fmaf(rv[i], INV_W, F_C);          // trunc: [0,95] guaranteed
            atomicAdd(&hist[b], 1);
        }
    }
    for (uint32_t k = CAP; __any_sync(FULLM, k < mycnt); k++) {   // rare remainder
        if (k < mycnt) {
            int b = (int)fmaf(gath[lane + k * 32], INV_W, F_C);
            atomicAdd(&hist[b], 1);
        }
    }
    __syncwarp();

    // ---- suffix scan of 96 band bins; locate boundary bin b* ----
    const int c0 = hist[3 * lane], c1 = hist[3 * lane + 1], c2 = hist[3 * lane + 2];
    const int own = c0 + c1 + c2;
    int inc = own;
    #pragma unroll
    for (int o = 1; o < 32; o <<= 1) {
        int v = __shfl_down_sync(FULLM, inc, o);
        if (lane + o < 32) inc += v;
    }
    const int exc   = inc - own;
    const int total = __shfl_sync(FULLM, inc, 0);          // band count
    const int c_hi  = c_ge - total;
    const int need  = KSEL - c_hi;

    bool fb = (need <= 0) || (total < need);

    int bstar = 0, above = 0;
    {
        bool here = !fb && (exc < need) && (need <= inc);
        int lb = 0, la = 0;
        if (here) {
            if      (exc + c2 >= need)      { lb = 3 * lane + 2; la = exc; }
            else if (exc + c2 + c1 >= need) { lb = 3 * lane + 1; la = exc + c2; }
            else                            { lb = 3 * lane;     la = exc + c2 + c1; }
        }
        unsigned bal = __ballot_sync(FULLM, here);
        if (bal == 0) fb = true;
        else {
            int src = __ffs(bal) - 1;
            bstar = __shfl_sync(FULLM, lb, src);
            above = __shfl_sync(FULLM, la, src);
        }
    }

    float loss = 0.f;    // valid on lane 0

    if (!fb) {
        // ---- pass 3: subtract bins < b*; gather boundary == b* (from registers) ----
        float sub = 0.f;
        #pragma unroll
        for (int i = 0; i < CAP; i++) {
            if ((uint32_t)i < mycnt) {
                int b = (int)fmaf(rv[i], INV_W, F_C);
                if (b < bstar) sub += rv[i];
                else if (b == bstar) {
                    int i2 = atomicAdd(&s_bcnt[w], 1);
                    if (i2 < BBUFN) s_bbuf[w][i2] = rv[i];
                }
            }
        }
        for (uint32_t k = CAP; __any_sync(FULLM, k < mycnt); k++) {   // rare remainder
            if (k < mycnt) {
                float x = gath[lane + k * 32];
                int b = (int)fmaf(x, INV_W, F_C);
                if (b < bstar) sub += x;
                else if (b == bstar) {
                    int i2 = atomicAdd(&s_bcnt[w], 1);
                    if (i2 < BBUFN) s_bbuf[w][i2] = x;
                }
            }
        }
        __syncwarp();
        const int mm = s_bcnt[w];
        if (mm > BBUFN) fb = true;
        else {
            const int r = need - above;                // keep r largest of boundary
            if (lane < mm) {
                unsigned mv = __float_as_uint(s_bbuf[w][lane]);  // positive: int order
                int rk = 0;
                for (int j = 0; j < mm; j++) {
                    unsigned xv = __float_as_uint(s_bbuf[w][j]);
                    rk += (xv > mv) || (xv == mv && j < lane);
                }
                if (rk >= r) sub += __uint_as_float(mv);         // excluded
            }
            sub = warpSumF(sub);
            if (lane == 0) {
                float p = (S_all - sub) * (1.0f / KSEL);
                loss = t * __logf(p) + (1.0f - t) * __logf(1.0f - p);
            }
        }
    }

    if (fb) {
        // ---- exact fallback: radix select, reload (L1/L2-hot, rare) ----
        unsigned prefix = 0;
        for (int bit = 30; bit >= 0; bit--) {
            unsigned test = prefix | (1u << bit);
            int cc = 0;
            #pragma unroll
            for (int c = 0; c < 8; c++) {
                float4 q = base[lane + c * 32];
                cc += (__float_as_uint(q.x) >= test) + (__float_as_uint(q.y) >= test)
                    + (__float_as_uint(q.z) >= test) + (__float_as_uint(q.w) >= test);
            }
            cc = __reduce_add_sync(FULLM, cc);
            if (cc >= KSEL) prefix = test;
        }
        float Sf = 0.f; int G = 0;
        #pragma unroll
        for (int c = 0; c < 8; c++) {
            float4 q = base[lane + c * 32];
            if (__float_as_uint(q.x) > prefix) { G++; Sf += q.x; }
            if (__float_as_uint(q.y) > prefix) { G++; Sf += q.y; }
            if (__float_as_uint(q.z) > prefix) { G++; Sf += q.z; }
            if (__float_as_uint(q.w) > prefix) { G++; Sf += q.w; }
        }
        Sf = warpSumF(Sf);
        G = __reduce_add_sync(FULLM, G);
        if (lane == 0) {
            float kthv = __uint_as_float(prefix);
            float p = (Sf + (float)(KSEL - G) * kthv) * (1.0f / KSEL);
            loss = t * __logf(p) + (1.0f - t) * __logf(1.0f - p);
        }
    }

    if (lane == 0) atomicAdd(&g_part[seg & (NSLOT - 1)], loss);

    // ---- fused finalize: last block reduces the 256 partials ----
    __syncthreads();
    if (tid == 0) {
        __threadfence();
        unsigned old = atomicAdd(&g_done, 1u);
        s_islast = (old == NBLK - 1) ? 1 : 0;
    }
    __syncthreads();
    if (s_islast) {
        __threadfence();
        float v = g_part[tid];
        g_part[tid] = 0.0f;                   // reset for next graph replay
        v = warpSumF(v);
        if (lane == 0) s_red[w] = v;
        __syncthreads();
        if (tid == 0) {
            float acc = 0.f;
            #pragma unroll
            for (int i = 0; i < WPB; i++) acc += s_red[i];
            out[0] = -acc * (1.0f / NSEG);
            g_done = 0;                       // reset for next graph replay
        }
    }
}

extern "C" void kernel_launch(void* const* d_in, const int* in_sizes, int n_in,
                              void* d_out, int out_size) {
    const float* y_pred = (const float*)d_in[0];
    const float* yv     = (const float*)d_in[1];
    (void)in_sizes; (void)n_in; (void)out_size;

    mil_kernel<<<NBLK, NTHR>>>(y_pred, yv, (float*)d_out);
}